// round 1
// baseline (speedup 1.0000x reference)
#include <cuda_runtime.h>
#include <math.h>
#include <stdint.h>

// ---------------------------------------------------------------------------
// LorentzTransformerEncoder  (B=8, N=1024, D=769, H=12, hd=64, M=3072) fp32
// ---------------------------------------------------------------------------

constexpr int B  = 8;
constexpr int N  = 1024;
constexpr int D  = 769;
constexpr int DS = 768;    // space dims
constexpr int H  = 12;
constexpr int HD = 64;
constexpr int M_ = 3072;
constexpr int MS = 3071;   // M-1
constexpr int BN = B * N;      // 8192
constexpr int BH = B * H;      // 96

// ------------------------------- scratch -----------------------------------
__device__ float g_h1  [(size_t)BN * D];     // LN1 output, [bn][769] (time at 0)
__device__ float g_qs  [(size_t)BN * DS];    // Q space  [bn][768]
__device__ float g_ksp [(size_t)BN * DS];    // K space
__device__ float g_vsp [(size_t)BN * DS];    // V space
__device__ float g_qt  [BH * N];             // per-head times [bh][i]
__device__ float g_kt  [BH * N];
__device__ float g_vt  [BH * N];
__device__ float g_lt  [(size_t)BH * N * N]; // transposed logits / probs [bh][j][i]
__device__ float g_s   [(size_t)BH * N * 80];// attn out per head, 65 used of 80 [bh][j][d]
__device__ float g_attn[(size_t)BN * D];     // reassembled attn [bn][769]
__device__ float g_out1[(size_t)BN * DS];    // residual stream (space only)
__device__ float g_z   [(size_t)BN * D];     // LN2 output [bn][769]
__device__ float g_hcat[(size_t)BN * M_];    // FFN hidden incl. time at col 0

// ----------------------------- reductions ----------------------------------
__device__ __forceinline__ float block_reduce_sum(float v, float* sh) {
    int tid = threadIdx.x, lane = tid & 31, wid = tid >> 5;
    #pragma unroll
    for (int o = 16; o > 0; o >>= 1) v += __shfl_down_sync(0xffffffffu, v, o);
    __syncthreads();
    if (lane == 0) sh[wid] = v;
    __syncthreads();
    if (tid == 0) {
        float s = 0.f;
        #pragma unroll
        for (int w = 0; w < 8; w++) s += sh[w];
        sh[32] = s;
    }
    __syncthreads();
    return sh[32];
}

__device__ __forceinline__ float block_reduce_max(float v, float* sh) {
    int tid = threadIdx.x, lane = tid & 31, wid = tid >> 5;
    #pragma unroll
    for (int o = 16; o > 0; o >>= 1) v = fmaxf(v, __shfl_down_sync(0xffffffffu, v, o));
    __syncthreads();
    if (lane == 0) sh[wid] = v;
    __syncthreads();
    if (tid == 0) {
        float m = sh[0];
        #pragma unroll
        for (int w = 1; w < 8; w++) m = fmaxf(m, sh[w]);
        sh[32] = m;
    }
    __syncthreads();
    return sh[32];
}

// ------------------------- Lorentz layernorm --------------------------------
// Y[bn][0] = sqrt(1 + |ys|^2), Y[bn][1+d] = gamma[d]*(x-mu)*rstd + beta[d]
__global__ void ln_kernel(const float* __restrict__ X, int ldx, int xofs,
                          const float* __restrict__ gamma,
                          const float* __restrict__ beta,
                          float* __restrict__ Y) {
    __shared__ float sh[33];
    int bn = blockIdx.x, tid = threadIdx.x;
    const float* x = X + (size_t)bn * ldx + xofs;
    float v[3], s = 0.f;
    #pragma unroll
    for (int i = 0; i < 3; i++) { v[i] = x[tid + i * 256]; s += v[i]; }
    s = block_reduce_sum(s, sh);
    float mu = s * (1.f / 768.f);
    float s2 = 0.f;
    #pragma unroll
    for (int i = 0; i < 3; i++) { float dd = v[i] - mu; s2 += dd * dd; }
    s2 = block_reduce_sum(s2, sh);
    float rstd = rsqrtf(s2 * (1.f / 768.f) + 1e-5f);
    float t2 = 0.f;
    float* y = Y + (size_t)bn * D;
    #pragma unroll
    for (int i = 0; i < 3; i++) {
        int d = tid + i * 256;
        float yy = gamma[d] * (v[i] - mu) * rstd + beta[d];
        y[1 + d] = yy;
        t2 += yy * yy;
    }
    t2 = block_reduce_sum(t2, sh);
    if (tid == 0) y[0] = sqrtf(1.f + t2);
}

// ------------------------------ SGEMM ---------------------------------------
// C[m][n] = sum_k A[m][k] * W[n + wofs][k]   ; EPI: 0=none, 1=gelu(tanh), 2=+R
// M is fixed 8192 (grid.y * 64). Guards on Nn and Kk.
template<int EPI>
__global__ void __launch_bounds__(256)
sgemm(const float* __restrict__ A, int lda,
      const float* __restrict__ W, int ldw, int wofs,
      float* __restrict__ C, int ldc, int cofs,
      const float* __restrict__ R, int ldr, int rofs,
      int Nn, int Kk) {
    __shared__ float As[16][64];
    __shared__ float Ws[16][64];
    int bm = blockIdx.y << 6, bn = blockIdx.x << 6;
    int tx = threadIdx.x, ty = threadIdx.y, tid = ty * 16 + tx;
    int lr = tid >> 2, lc = (tid & 3) << 2;
    float acc[4][4] = {};
    const float* ap = A + (size_t)(bm + lr) * lda + lc;
    bool wrow_ok = (bn + lr) < Nn;
    const float* wp = W + (size_t)(bn + lr + wofs) * ldw + lc;
    for (int k0 = 0; k0 < Kk; k0 += 16) {
        #pragma unroll
        for (int c = 0; c < 4; c++) {
            int k = k0 + lc + c;
            As[lc + c][lr] = (k < Kk) ? ap[k0 + c] : 0.f;
            Ws[lc + c][lr] = (wrow_ok && k < Kk) ? wp[k0 + c] : 0.f;
        }
        __syncthreads();
        #pragma unroll
        for (int kk = 0; kk < 16; kk++) {
            float a[4], b[4];
            #pragma unroll
            for (int i = 0; i < 4; i++) a[i] = As[kk][(ty << 2) + i];
            #pragma unroll
            for (int j = 0; j < 4; j++) b[j] = Ws[kk][(tx << 2) + j];
            #pragma unroll
            for (int i = 0; i < 4; i++)
                #pragma unroll
                for (int j = 0; j < 4; j++)
                    acc[i][j] = fmaf(a[i], b[j], acc[i][j]);
        }
        __syncthreads();
    }
    #pragma unroll
    for (int i = 0; i < 4; i++) {
        int m = bm + (ty << 2) + i;
        #pragma unroll
        for (int j = 0; j < 4; j++) {
            int n = bn + (tx << 2) + j;
            if (n < Nn) {
                float v = acc[i][j];
                if (EPI == 1) {
                    float xx = v;
                    float t = tanhf(0.7978845608028654f * (xx + 0.044715f * xx * xx * xx));
                    v = 0.5f * xx * (1.f + t);
                }
                if (EPI == 2) v += R[(size_t)m * ldr + rofs + n];
                C[(size_t)m * ldc + cofs + n] = v;
            }
        }
    }
}

// ----------------------- per-head time recompute ----------------------------
__global__ void head_time_kernel(const float* __restrict__ S, float* __restrict__ T) {
    int idx = blockIdx.x * 256 + threadIdx.x;
    if (idx >= BH * N) return;
    int i = idx & (N - 1);
    int bh = idx >> 10;
    int h = bh % H, b = bh / H;
    const float* p = S + (size_t)(b * N + i) * DS + h * HD;
    float s = 1.f;
    #pragma unroll 16
    for (int d = 0; d < HD; d++) s = fmaf(p[d], p[d], s);
    T[idx] = sqrtf(s);
}

// ----------------------------- logits ---------------------------------------
// g_lt[bh][j][i] = 1 / (1 + log1p(max(2*(kt[j]qt[i] - ks[j].qs[i] - 1), 1e-8)))
__global__ void __launch_bounds__(256) logits_kernel() {
    int bh = blockIdx.z;
    int b = bh / H, h = bh % H;
    int j0 = blockIdx.y << 6, i0 = blockIdx.x << 6;
    __shared__ float Ksm[64][65];
    __shared__ float Qsm[64][65];
    int tx = threadIdx.x, ty = threadIdx.y, tid = ty * 16 + tx;
    int lr = tid >> 2, lc = (tid & 3) << 4;
    const float* kp = g_ksp + (size_t)(b * N + j0 + lr) * DS + h * HD + lc;
    const float* qp = g_qs  + (size_t)(b * N + i0 + lr) * DS + h * HD + lc;
    #pragma unroll
    for (int c = 0; c < 16; c++) { Ksm[lr][lc + c] = kp[c]; Qsm[lr][lc + c] = qp[c]; }
    __syncthreads();
    float acc[4][4] = {};
    #pragma unroll 4
    for (int d = 0; d < 64; d++) {
        float kv[4], qv[4];
        #pragma unroll
        for (int jj = 0; jj < 4; jj++) kv[jj] = Ksm[(ty << 2) + jj][d];
        #pragma unroll
        for (int ii = 0; ii < 4; ii++) qv[ii] = Qsm[(tx << 2) + ii][d];
        #pragma unroll
        for (int jj = 0; jj < 4; jj++)
            #pragma unroll
            for (int ii = 0; ii < 4; ii++)
                acc[jj][ii] = fmaf(kv[jj], qv[ii], acc[jj][ii]);
    }
    float ktv[4], qtv[4];
    #pragma unroll
    for (int jj = 0; jj < 4; jj++) ktv[jj] = g_kt[bh * N + j0 + (ty << 2) + jj];
    #pragma unroll
    for (int ii = 0; ii < 4; ii++) qtv[ii] = g_qt[bh * N + i0 + (tx << 2) + ii];
    #pragma unroll
    for (int jj = 0; jj < 4; jj++) {
        size_t rowbase = ((size_t)bh * N + j0 + (ty << 2) + jj) * N + i0;
        #pragma unroll
        for (int ii = 0; ii < 4; ii++) {
            float mi = ktv[jj] * qtv[ii] - acc[jj][ii];
            float d2 = fmaxf(2.f * (mi - 1.f), 1e-8f);
            g_lt[rowbase + (tx << 2) + ii] = 1.f / (1.f + log1pf(d2));
        }
    }
}

// ----------------------------- softmax (rows of g_lt) ------------------------
__global__ void softmax_kernel() {
    __shared__ float sh[33];
    size_t row = blockIdx.x;
    float* p = g_lt + row * N;
    int tid = threadIdx.x;
    float v[4], mx = -1e30f;
    #pragma unroll
    for (int i = 0; i < 4; i++) { v[i] = p[tid + i * 256]; mx = fmaxf(mx, v[i]); }
    mx = block_reduce_max(mx, sh);
    float s = 0.f;
    #pragma unroll
    for (int i = 0; i < 4; i++) { v[i] = expf(v[i] - mx); s += v[i]; }
    s = block_reduce_sum(s, sh);
    float inv = 1.f / s;
    #pragma unroll
    for (int i = 0; i < 4; i++) p[tid + i * 256] = v[i] * inv;
}

// ------------------------------- P @ V_cat ----------------------------------
// g_s[bh][j][d], d=0 time (Vt), d=1..64 space
__global__ void __launch_bounds__(256) av_kernel() {
    int bh = blockIdx.y;
    int b = bh / H, h = bh % H;
    int j0 = blockIdx.x << 6;
    __shared__ float Psm[64][65];
    __shared__ float Vsm[64][66];
    int tx = threadIdx.x, ty = threadIdx.y, tid = ty * 16 + tx;
    int lr = tid >> 2, lc = (tid & 3) << 4;
    float acc[4][5] = {};
    for (int i0 = 0; i0 < N; i0 += 64) {
        const float* pp = g_lt  + ((size_t)bh * N + j0 + lr) * N + i0 + lc;
        const float* vp = g_vsp + (size_t)(b * N + i0 + lr) * DS + h * HD + lc;
        #pragma unroll
        for (int c = 0; c < 16; c++) { Psm[lr][lc + c] = pp[c]; Vsm[lr][1 + lc + c] = vp[c]; }
        if ((tid & 3) == 0) Vsm[lr][0] = g_vt[bh * N + i0 + lr];
        __syncthreads();
        #pragma unroll 4
        for (int ii = 0; ii < 64; ii++) {
            float pv[4];
            #pragma unroll
            for (int jj = 0; jj < 4; jj++) pv[jj] = Psm[(ty << 2) + jj][ii];
            float vv[5];
            #pragma unroll
            for (int c = 0; c < 4; c++) vv[c] = Vsm[ii][tx + 16 * c];
            vv[4] = Vsm[ii][64];
            #pragma unroll
            for (int jj = 0; jj < 4; jj++) {
                #pragma unroll
                for (int c = 0; c < 5; c++)
                    acc[jj][c] = fmaf(pv[jj], vv[c], acc[jj][c]);
            }
        }
        __syncthreads();
    }
    #pragma unroll
    for (int jj = 0; jj < 4; jj++) {
        size_t base = ((size_t)bh * N + j0 + (ty << 2) + jj) * 80;
        #pragma unroll
        for (int c = 0; c < 4; c++) g_s[base + tx + 16 * c] = acc[jj][c];
        if (tx == 0) g_s[base + 64] = acc[jj][4];
    }
}

// --------- per-head hyperboloid normalize + head-concat + new time ----------
__global__ void assemble_kernel() {
    __shared__ float hsum[12];
    __shared__ float hinv[12];
    __shared__ float cts;
    int bn = blockIdx.x;
    int b = bn >> 10, j = bn & (N - 1);
    int tid = threadIdx.x;
    if (tid < 12) hsum[tid] = 0.f;
    if (tid == 0) cts = 0.f;
    __syncthreads();
    float sv[3];
    #pragma unroll
    for (int r = 0; r < 3; r++) {
        int e = tid + r * 256;
        int h = e >> 6, d = e & 63;
        sv[r] = g_s[((size_t)(b * H + h) * N + j) * 80 + 1 + d];
        atomicAdd(&hsum[h], sv[r] * sv[r]);
    }
    __syncthreads();
    if (tid < 12) {
        float st = g_s[((size_t)(b * H + tid) * N + j) * 80];
        float li = st * st - hsum[tid];
        float inv = rsqrtf(fmaxf(li, 1e-8f));
        hinv[tid] = inv;
        float ct = st * inv;
        atomicAdd(&cts, ct * ct);
    }
    __syncthreads();
    float* out = g_attn + (size_t)bn * D;
    #pragma unroll
    for (int r = 0; r < 3; r++) {
        int e = tid + r * 256;
        int h = e >> 6;
        out[1 + e] = sv[r] * hinv[h];
    }
    if (tid == 0) out[0] = sqrtf(cts - 11.f);  // sum ct^2 - (H-1)*K
}

// --------------------- FFN hidden time (col 0 of g_hcat) --------------------
__global__ void hcat_time_kernel() {
    __shared__ float sh[33];
    int bn = blockIdx.x, tid = threadIdx.x;
    const float* p = g_hcat + (size_t)bn * M_;
    float s = 0.f;
    for (int d = 1 + tid; d < M_; d += 256) s = fmaf(p[d], p[d], s);
    s = block_reduce_sum(s, sh);
    if (tid == 0) g_hcat[(size_t)bn * M_] = sqrtf(1.f + s);
}

// --------------------------- final add_time ---------------------------------
__global__ void final_time_kernel(float* __restrict__ out) {
    __shared__ float sh[33];
    int bn = blockIdx.x, tid = threadIdx.x;
    float* p = out + (size_t)bn * D;
    float s = 0.f;
    #pragma unroll
    for (int r = 0; r < 3; r++) {
        int d = tid + r * 256;
        float v = p[1 + d];
        s = fmaf(v, v, s);
    }
    s = block_reduce_sum(s, sh);
    if (tid == 0) p[0] = sqrtf(1.f + s);
}

// ----------------------------------------------------------------------------
extern "C" void kernel_launch(void* const* d_in, const int* in_sizes, int n_in,
                              void* d_out, int out_size) {
    const float* x      = (const float*)d_in[0];
    const float* gamma1 = (const float*)d_in[1];
    const float* beta1  = (const float*)d_in[2];
    const float* Wq     = (const float*)d_in[3];
    const float* Wk     = (const float*)d_in[4];
    const float* Wv     = (const float*)d_in[5];
    const float* Wo     = (const float*)d_in[6];
    const float* gamma2 = (const float*)d_in[7];
    const float* beta2  = (const float*)d_in[8];
    const float* W1     = (const float*)d_in[9];
    const float* W2     = (const float*)d_in[10];
    float* out = (float*)d_out;

    float *h1, *qs, *ksp, *vsp, *qt, *kt, *vt, *attn, *out1, *z, *hcat;
    cudaGetSymbolAddress((void**)&h1,   g_h1);
    cudaGetSymbolAddress((void**)&qs,   g_qs);
    cudaGetSymbolAddress((void**)&ksp,  g_ksp);
    cudaGetSymbolAddress((void**)&vsp,  g_vsp);
    cudaGetSymbolAddress((void**)&qt,   g_qt);
    cudaGetSymbolAddress((void**)&kt,   g_kt);
    cudaGetSymbolAddress((void**)&vt,   g_vt);
    cudaGetSymbolAddress((void**)&attn, g_attn);
    cudaGetSymbolAddress((void**)&out1, g_out1);
    cudaGetSymbolAddress((void**)&z,    g_z);
    cudaGetSymbolAddress((void**)&hcat, g_hcat);

    dim3 t2(16, 16);
    dim3 gemm768(12, 128);   // N=768
    dim3 gemmFF1(48, 128);   // N=3071

    // 1) LN1
    ln_kernel<<<BN, 256>>>(x, D, 1, gamma1, beta1, h1);

    // 2) QKV projections (space part only; per-head time recomputed)
    sgemm<0><<<gemm768, t2>>>(h1, D, Wq, D, 1, qs,  DS, 0, nullptr, 0, 0, DS, D);
    sgemm<0><<<gemm768, t2>>>(h1, D, Wk, D, 1, ksp, DS, 0, nullptr, 0, 0, DS, D);
    sgemm<0><<<gemm768, t2>>>(h1, D, Wv, D, 1, vsp, DS, 0, nullptr, 0, 0, DS, D);
    head_time_kernel<<<(BH * N + 255) / 256, 256>>>(qs,  qt);
    head_time_kernel<<<(BH * N + 255) / 256, 256>>>(ksp, kt);
    head_time_kernel<<<(BH * N + 255) / 256, 256>>>(vsp, vt);

    // 3) transposed logits -> row softmax -> P @ V_cat
    logits_kernel<<<dim3(16, 16, BH), t2>>>();
    softmax_kernel<<<BH * N, 256>>>();
    av_kernel<<<dim3(16, BH), t2>>>();

    // 4) hyperboloid normalize per head, concat heads, new time
    assemble_kernel<<<BN, 256>>>();

    // 5) Wo projection + residual with x (space part)
    sgemm<2><<<gemm768, t2>>>(attn, D, Wo, D, 1, out1, DS, 0, x, D, 1, DS, D);

    // 6) LN2
    ln_kernel<<<BN, 256>>>(out1, DS, 0, gamma2, beta2, z);

    // 7) FFN: gelu(z @ W1^T)[1:] -> hcat cols 1..3071 ; col 0 = time
    sgemm<1><<<gemmFF1, t2>>>(z, D, W1, D, 1, hcat, M_, 1, nullptr, 0, 0, MS, D);
    hcat_time_kernel<<<BN, 256>>>();

    // 8) FFN out: (hcat @ W2^T)[1:] + out1 -> d_out space cols
    sgemm<2><<<gemm768, t2>>>(hcat, M_, W2, M_, 1, out, D, 1, out1, DS, 0, DS, M_);

    // 9) final add_time
    final_time_kernel<<<BN, 256>>>(out);
}

// round 3
// speedup vs baseline: 1.6137x; 1.6137x over previous
#include <cuda_runtime.h>
#include <math.h>
#include <stdint.h>

// ---------------------------------------------------------------------------
// LorentzTransformerEncoder  (B=8, N=1024, D=769, H=12, hd=64, M=3072)
// R3 = R2 resubmit (infra failure): tf32 tensor-core GEMMs for QKV/Wo/FFN
// + attention logits; fused head_time over Q/K/V.
// ---------------------------------------------------------------------------

constexpr int B  = 8;
constexpr int N  = 1024;
constexpr int D  = 769;
constexpr int DS = 768;
constexpr int H  = 12;
constexpr int HD = 64;
constexpr int M_ = 3072;
constexpr int MS = 3071;
constexpr int BN = B * N;   // 8192
constexpr int BH = B * H;   // 96

// ------------------------------- scratch -----------------------------------
__device__ float g_h1  [(size_t)BN * D];
__device__ float g_qs  [(size_t)BN * DS];
__device__ float g_ksp [(size_t)BN * DS];
__device__ float g_vsp [(size_t)BN * DS];
__device__ float g_qt  [BH * N];
__device__ float g_kt  [BH * N];
__device__ float g_vt  [BH * N];
__device__ float g_lt  [(size_t)BH * N * N];
__device__ float g_s   [(size_t)BH * N * 80];
__device__ float g_attn[(size_t)BN * D];
__device__ float g_out1[(size_t)BN * DS];
__device__ float g_z   [(size_t)BN * D];
__device__ float g_hcat[(size_t)BN * M_];

// ----------------------------- reductions ----------------------------------
__device__ __forceinline__ float block_reduce_sum(float v, float* sh) {
    int tid = threadIdx.x, lane = tid & 31, wid = tid >> 5;
    #pragma unroll
    for (int o = 16; o > 0; o >>= 1) v += __shfl_down_sync(0xffffffffu, v, o);
    __syncthreads();
    if (lane == 0) sh[wid] = v;
    __syncthreads();
    if (tid == 0) {
        float s = 0.f;
        #pragma unroll
        for (int w = 0; w < 8; w++) s += sh[w];
        sh[32] = s;
    }
    __syncthreads();
    return sh[32];
}

__device__ __forceinline__ float block_reduce_max(float v, float* sh) {
    int tid = threadIdx.x, lane = tid & 31, wid = tid >> 5;
    #pragma unroll
    for (int o = 16; o > 0; o >>= 1) v = fmaxf(v, __shfl_down_sync(0xffffffffu, v, o));
    __syncthreads();
    if (lane == 0) sh[wid] = v;
    __syncthreads();
    if (tid == 0) {
        float m = sh[0];
        #pragma unroll
        for (int w = 1; w < 8; w++) m = fmaxf(m, sh[w]);
        sh[32] = m;
    }
    __syncthreads();
    return sh[32];
}

// ------------------------- Lorentz layernorm --------------------------------
__global__ void ln_kernel(const float* __restrict__ X, int ldx, int xofs,
                          const float* __restrict__ gamma,
                          const float* __restrict__ beta,
                          float* __restrict__ Y) {
    __shared__ float sh[33];
    int bn = blockIdx.x, tid = threadIdx.x;
    const float* x = X + (size_t)bn * ldx + xofs;
    float v[3], s = 0.f;
    #pragma unroll
    for (int i = 0; i < 3; i++) { v[i] = x[tid + i * 256]; s += v[i]; }
    s = block_reduce_sum(s, sh);
    float mu = s * (1.f / 768.f);
    float s2 = 0.f;
    #pragma unroll
    for (int i = 0; i < 3; i++) { float dd = v[i] - mu; s2 += dd * dd; }
    s2 = block_reduce_sum(s2, sh);
    float rstd = rsqrtf(s2 * (1.f / 768.f) + 1e-5f);
    float t2 = 0.f;
    float* y = Y + (size_t)bn * D;
    #pragma unroll
    for (int i = 0; i < 3; i++) {
        int d = tid + i * 256;
        float yy = gamma[d] * (v[i] - mu) * rstd + beta[d];
        y[1 + d] = yy;
        t2 += yy * yy;
    }
    t2 = block_reduce_sum(t2, sh);
    if (tid == 0) y[0] = sqrtf(1.f + t2);
}

// ------------------------------ tf32 MMA helpers ----------------------------
__device__ __forceinline__ uint32_t cvt_tf32(float x) {
    uint32_t r;
    asm("cvt.rna.tf32.f32 %0, %1;" : "=r"(r) : "f"(x));
    return r;
}

__device__ __forceinline__ void ldsm4(uint32_t& r0, uint32_t& r1, uint32_t& r2,
                                      uint32_t& r3, uint32_t addr) {
    asm volatile("ldmatrix.sync.aligned.m8n8.x4.shared.b16 {%0,%1,%2,%3},[%4];"
                 : "=r"(r0), "=r"(r1), "=r"(r2), "=r"(r3) : "r"(addr));
}

__device__ __forceinline__ void mma_tf32(float* c, const uint32_t* a, const uint32_t* b) {
    asm volatile("mma.sync.aligned.m16n8k8.row.col.f32.tf32.tf32.f32 "
                 "{%0,%1,%2,%3},{%4,%5,%6,%7},{%8,%9},{%0,%1,%2,%3};"
                 : "+f"(c[0]), "+f"(c[1]), "+f"(c[2]), "+f"(c[3])
                 : "r"(a[0]), "r"(a[1]), "r"(a[2]), "r"(a[3]), "r"(b[0]), "r"(b[1]));
}

// ------------------------------- tf32 GEMM ----------------------------------
// C[m][n] = sum_k A[m][k] * Bm[n + bofs][k]
// EPI: 0 none, 1 gelu(tanh), 2 +R, 3 lorentz-attention-logit
// HM : per-head batch addressing (blockIdx.z = b*H + h)
// Tiles: 128x128x16, 256 threads, 8 warps (2m x 4n), warp 64x32.
template<int EPI, bool HM>
__global__ void __launch_bounds__(256)
mma_gemm(const float* __restrict__ A, int lda,
         const float* __restrict__ Bm, int ldb, int bofs,
         float* __restrict__ C, int ldc, int cofs, size_t cBatch,
         const float* __restrict__ R, int ldr, int rofs,
         const float* __restrict__ tA, const float* __restrict__ tB,
         int Nn, int Kk) {
    __shared__ uint32_t sA[2][128 * 20];
    __shared__ uint32_t sB[2][128 * 20];

    int tid = threadIdx.x;
    int lane = tid & 31, wid = tid >> 5;
    int warpm = wid >> 2, warpn = wid & 3;
    int bm = blockIdx.y << 7, bnb = blockIdx.x << 7;

    const float* Ab = A;
    const float* Bb = Bm;
    const float* tAp = tA;
    const float* tBp = tB;
    if (HM) {
        int bz = blockIdx.z;
        int b = bz / H, h = bz % H;
        Ab += (size_t)b * N * lda + h * HD;
        Bb += (size_t)b * N * ldb + h * HD;
        tAp = tA + (size_t)bz * N;
        tBp = tB + (size_t)bz * N;
        C += (size_t)bz * cBatch;
    }

    // loader mapping: each thread loads 8 consecutive k of one row, twice (A,B)
    int lrow = tid >> 1;
    int lkc  = (tid & 1) << 3;
    const float* aptr = Ab + (size_t)(bm + lrow) * lda + lkc;
    int brow = bnb + lrow;
    bool brow_ok = brow < Nn;
    const float* bptr = Bb + (size_t)(brow + bofs) * ldb + lkc;

    // ldmatrix per-lane addresses
    int aRow = warpm * 64 + (lane & 7) + ((lane >> 3) & 1) * 8;
    int aCol = ((lane >> 4) & 1) * 4;
    int bRow = warpn * 32 + (lane & 7) + ((lane >> 4) & 1) * 8;
    int bCol = ((lane >> 3) & 1) * 4;
    uint32_t aBase0 = (uint32_t)__cvta_generic_to_shared(&sA[0][aRow * 20 + aCol]);
    uint32_t aBase1 = (uint32_t)__cvta_generic_to_shared(&sA[1][aRow * 20 + aCol]);
    uint32_t bBase0 = (uint32_t)__cvta_generic_to_shared(&sB[0][bRow * 20 + bCol]);
    uint32_t bBase1 = (uint32_t)__cvta_generic_to_shared(&sB[1][bRow * 20 + bCol]);

    float acc[4][4][4];
    #pragma unroll
    for (int i = 0; i < 4; i++)
        #pragma unroll
        for (int j = 0; j < 4; j++)
            #pragma unroll
            for (int r = 0; r < 4; r++) acc[i][j][r] = 0.f;

    int iters = (Kk + 15) >> 4;

    // prefetch iter 0 into buf 0
    {
        uint32_t ra[8], rb[8];
        #pragma unroll
        for (int i = 0; i < 8; i++) {
            int k = lkc + i;
            ra[i] = (k < Kk) ? cvt_tf32(__ldg(aptr + i)) : 0u;
            rb[i] = (brow_ok && k < Kk) ? cvt_tf32(__ldg(bptr + i)) : 0u;
        }
        #pragma unroll
        for (int i = 0; i < 8; i++) {
            sA[0][lrow * 20 + lkc + i] = ra[i];
            sB[0][lrow * 20 + lkc + i] = rb[i];
        }
    }
    __syncthreads();

    for (int t = 0; t < iters; t++) {
        int buf = t & 1;
        uint32_t ra[8], rb[8];
        bool more = (t + 1) < iters;
        if (more) {
            int k0 = (t + 1) << 4;
            #pragma unroll
            for (int i = 0; i < 8; i++) {
                int k = k0 + lkc + i;
                ra[i] = (k < Kk) ? cvt_tf32(__ldg(aptr + k0 + i)) : 0u;
                rb[i] = (brow_ok && k < Kk) ? cvt_tf32(__ldg(bptr + k0 + i)) : 0u;
            }
        }

        uint32_t aB = buf ? aBase1 : aBase0;
        uint32_t bB = buf ? bBase1 : bBase0;
        #pragma unroll
        for (int ks = 0; ks < 2; ks++) {
            uint32_t af[4][4];
            uint32_t bf[4][2];
            #pragma unroll
            for (int mt = 0; mt < 4; mt++)
                ldsm4(af[mt][0], af[mt][1], af[mt][2], af[mt][3],
                      aB + mt * 1280 + ks * 32);
            #pragma unroll
            for (int np = 0; np < 2; np++)
                ldsm4(bf[2 * np][0], bf[2 * np][1], bf[2 * np + 1][0], bf[2 * np + 1][1],
                      bB + np * 1280 + ks * 32);
            #pragma unroll
            for (int mt = 0; mt < 4; mt++)
                #pragma unroll
                for (int nt = 0; nt < 4; nt++)
                    mma_tf32(acc[mt][nt], af[mt], bf[nt]);
        }

        if (more) {
            int obuf = buf ^ 1;
            #pragma unroll
            for (int i = 0; i < 8; i++) {
                sA[obuf][lrow * 20 + lkc + i] = ra[i];
                sB[obuf][lrow * 20 + lkc + i] = rb[i];
            }
        }
        __syncthreads();
    }

    // epilogue
    int er = bm + warpm * 64 + (lane >> 2);
    int ec0 = bnb + warpn * 32 + 2 * (lane & 3);
    #pragma unroll
    for (int mt = 0; mt < 4; mt++) {
        #pragma unroll
        for (int nt = 0; nt < 4; nt++) {
            #pragma unroll
            for (int half = 0; half < 2; half++) {
                int r = er + mt * 16 + half * 8;
                int c = ec0 + nt * 8;
                float v0 = acc[mt][nt][2 * half];
                float v1 = acc[mt][nt][2 * half + 1];
                if (EPI == 1) {
                    float t0 = tanhf(0.7978845608028654f * (v0 + 0.044715f * v0 * v0 * v0));
                    v0 = 0.5f * v0 * (1.f + t0);
                    float t1 = tanhf(0.7978845608028654f * (v1 + 0.044715f * v1 * v1 * v1));
                    v1 = 0.5f * v1 * (1.f + t1);
                }
                if (EPI == 2) {
                    const float* rp = R + (size_t)r * ldr + rofs;
                    if (c < Nn) v0 += rp[c];
                    if (c + 1 < Nn) v1 += rp[c + 1];
                }
                if (EPI == 3) {
                    float kt = tAp[r];
                    float mi0 = kt * tBp[c] - v0;
                    float mi1 = kt * tBp[(c + 1 < Nn) ? c + 1 : c] - v1;
                    float d20 = fmaxf(2.f * (mi0 - 1.f), 1e-8f);
                    float d21 = fmaxf(2.f * (mi1 - 1.f), 1e-8f);
                    v0 = 1.f / (1.f + log1pf(d20));
                    v1 = 1.f / (1.f + log1pf(d21));
                }
                float* cp = C + (size_t)r * ldc + cofs;
                if (c + 1 < Nn) {
                    cp[c] = v0; cp[c + 1] = v1;
                } else if (c < Nn) {
                    cp[c] = v0;
                }
            }
        }
    }
}

// ----------------------- per-head time recompute (Q,K,V fused) --------------
__global__ void head_time_kernel() {
    int idx = blockIdx.x * 256 + threadIdx.x;
    int which = blockIdx.y;
    if (idx >= BH * N) return;
    int i = idx & (N - 1);
    int bh = idx >> 10;
    int h = bh % H, b = bh / H;
    const float* S = (which == 0) ? g_qs : (which == 1) ? g_ksp : g_vsp;
    float* T = (which == 0) ? g_qt : (which == 1) ? g_kt : g_vt;
    const float* p = S + (size_t)(b * N + i) * DS + h * HD;
    float s = 1.f;
    #pragma unroll 16
    for (int d = 0; d < HD; d++) s = fmaf(p[d], p[d], s);
    T[idx] = sqrtf(s);
}

// ----------------------------- softmax (rows of g_lt) ------------------------
__global__ void softmax_kernel() {
    __shared__ float sh[33];
    size_t row = blockIdx.x;
    float* p = g_lt + row * N;
    int tid = threadIdx.x;
    float v[4], mx = -1e30f;
    #pragma unroll
    for (int i = 0; i < 4; i++) { v[i] = p[tid + i * 256]; mx = fmaxf(mx, v[i]); }
    mx = block_reduce_max(mx, sh);
    float s = 0.f;
    #pragma unroll
    for (int i = 0; i < 4; i++) { v[i] = expf(v[i] - mx); s += v[i]; }
    s = block_reduce_sum(s, sh);
    float inv = 1.f / s;
    #pragma unroll
    for (int i = 0; i < 4; i++) p[tid + i * 256] = v[i] * inv;
}

// ------------------------------- P @ V_cat ----------------------------------
__global__ void __launch_bounds__(256) av_kernel() {
    int bh = blockIdx.y;
    int b = bh / H, h = bh % H;
    int j0 = blockIdx.x << 6;
    __shared__ float Psm[64][65];
    __shared__ float Vsm[64][66];
    int tx = threadIdx.x, ty = threadIdx.y, tid = ty * 16 + tx;
    int lr = tid >> 2, lc = (tid & 3) << 4;
    float acc[4][5] = {};
    for (int i0 = 0; i0 < N; i0 += 64) {
        const float* pp = g_lt  + ((size_t)bh * N + j0 + lr) * N + i0 + lc;
        const float* vp = g_vsp + (size_t)(b * N + i0 + lr) * DS + h * HD + lc;
        #pragma unroll
        for (int c = 0; c < 16; c++) { Psm[lr][lc + c] = pp[c]; Vsm[lr][1 + lc + c] = vp[c]; }
        if ((tid & 3) == 0) Vsm[lr][0] = g_vt[bh * N + i0 + lr];
        __syncthreads();
        #pragma unroll 4
        for (int ii = 0; ii < 64; ii++) {
            float pv[4];
            #pragma unroll
            for (int jj = 0; jj < 4; jj++) pv[jj] = Psm[(ty << 2) + jj][ii];
            float vv[5];
            #pragma unroll
            for (int c = 0; c < 4; c++) vv[c] = Vsm[ii][tx + 16 * c];
            vv[4] = Vsm[ii][64];
            #pragma unroll
            for (int jj = 0; jj < 4; jj++) {
                #pragma unroll
                for (int c = 0; c < 5; c++)
                    acc[jj][c] = fmaf(pv[jj], vv[c], acc[jj][c]);
            }
        }
        __syncthreads();
    }
    #pragma unroll
    for (int jj = 0; jj < 4; jj++) {
        size_t base = ((size_t)bh * N + j0 + (ty << 2) + jj) * 80;
        #pragma unroll
        for (int c = 0; c < 4; c++) g_s[base + tx + 16 * c] = acc[jj][c];
        if (tx == 0) g_s[base + 64] = acc[jj][4];
    }
}

// --------- per-head hyperboloid normalize + head-concat + new time ----------
__global__ void assemble_kernel() {
    __shared__ float hsum[12];
    __shared__ float hinv[12];
    __shared__ float cts;
    int bn = blockIdx.x;
    int b = bn >> 10, j = bn & (N - 1);
    int tid = threadIdx.x;
    if (tid < 12) hsum[tid] = 0.f;
    if (tid == 0) cts = 0.f;
    __syncthreads();
    float sv[3];
    #pragma unroll
    for (int r = 0; r < 3; r++) {
        int e = tid + r * 256;
        int h = e >> 6, d = e & 63;
        sv[r] = g_s[((size_t)(b * H + h) * N + j) * 80 + 1 + d];
        atomicAdd(&hsum[h], sv[r] * sv[r]);
    }
    __syncthreads();
    if (tid < 12) {
        float st = g_s[((size_t)(b * H + tid) * N + j) * 80];
        float li = st * st - hsum[tid];
        float inv = rsqrtf(fmaxf(li, 1e-8f));
        hinv[tid] = inv;
        float ct = st * inv;
        atomicAdd(&cts, ct * ct);
    }
    __syncthreads();
    float* out = g_attn + (size_t)bn * D;
    #pragma unroll
    for (int r = 0; r < 3; r++) {
        int e = tid + r * 256;
        int h = e >> 6;
        out[1 + e] = sv[r] * hinv[h];
    }
    if (tid == 0) out[0] = sqrtf(cts - 11.f);
}

// --------------------- FFN hidden time (col 0 of g_hcat) --------------------
__global__ void hcat_time_kernel() {
    __shared__ float sh[33];
    int bn = blockIdx.x, tid = threadIdx.x;
    const float* p = g_hcat + (size_t)bn * M_;
    float s = 0.f;
    for (int d = 1 + tid; d < M_; d += 256) s = fmaf(p[d], p[d], s);
    s = block_reduce_sum(s, sh);
    if (tid == 0) g_hcat[(size_t)bn * M_] = sqrtf(1.f + s);
}

// --------------------------- final add_time ---------------------------------
__global__ void final_time_kernel(float* __restrict__ out) {
    __shared__ float sh[33];
    int bn = blockIdx.x, tid = threadIdx.x;
    float* p = out + (size_t)bn * D;
    float s = 0.f;
    #pragma unroll
    for (int r = 0; r < 3; r++) {
        int d = tid + r * 256;
        float v = p[1 + d];
        s = fmaf(v, v, s);
    }
    s = block_reduce_sum(s, sh);
    if (tid == 0) p[0] = sqrtf(1.f + s);
}

// ----------------------------------------------------------------------------
extern "C" void kernel_launch(void* const* d_in, const int* in_sizes, int n_in,
                              void* d_out, int out_size) {
    const float* x      = (const float*)d_in[0];
    const float* gamma1 = (const float*)d_in[1];
    const float* beta1  = (const float*)d_in[2];
    const float* Wq     = (const float*)d_in[3];
    const float* Wk     = (const float*)d_in[4];
    const float* Wv     = (const float*)d_in[5];
    const float* Wo     = (const float*)d_in[6];
    const float* gamma2 = (const float*)d_in[7];
    const float* beta2  = (const float*)d_in[8];
    const float* W1     = (const float*)d_in[9];
    const float* W2     = (const float*)d_in[10];
    float* out = (float*)d_out;

    float *h1, *qs, *ksp, *vsp, *qt, *kt, *vt, *lt, *attn, *out1, *z, *hcat;
    cudaGetSymbolAddress((void**)&h1,   g_h1);
    cudaGetSymbolAddress((void**)&qs,   g_qs);
    cudaGetSymbolAddress((void**)&ksp,  g_ksp);
    cudaGetSymbolAddress((void**)&vsp,  g_vsp);
    cudaGetSymbolAddress((void**)&qt,   g_qt);
    cudaGetSymbolAddress((void**)&kt,   g_kt);
    cudaGetSymbolAddress((void**)&vt,   g_vt);
    cudaGetSymbolAddress((void**)&lt,   g_lt);
    cudaGetSymbolAddress((void**)&attn, g_attn);
    cudaGetSymbolAddress((void**)&out1, g_out1);
    cudaGetSymbolAddress((void**)&z,    g_z);
    cudaGetSymbolAddress((void**)&hcat, g_hcat);

    dim3 t1(256);
    dim3 g768(6, 64);     // N=768,  M=8192
    dim3 gFF1(24, 64);    // N=3071, M=8192
    dim3 gLog(8, 8, BH);  // logits: 1024x1024 x 96

    // 1) LN1
    ln_kernel<<<BN, 256>>>(x, D, 1, gamma1, beta1, h1);

    // 2) QKV projections (tf32 MMA)
    mma_gemm<0, false><<<g768, t1>>>(h1, D, Wq, D, 1, qs,  DS, 0, 0, nullptr, 0, 0, nullptr, nullptr, DS, D);
    mma_gemm<0, false><<<g768, t1>>>(h1, D, Wk, D, 1, ksp, DS, 0, 0, nullptr, 0, 0, nullptr, nullptr, DS, D);
    mma_gemm<0, false><<<g768, t1>>>(h1, D, Wv, D, 1, vsp, DS, 0, 0, nullptr, 0, 0, nullptr, nullptr, DS, D);
    head_time_kernel<<<dim3((BH * N + 255) / 256, 3), 256>>>();

    // 3) transposed logits (tf32 MMA, per-head) -> row softmax -> P @ V_cat
    mma_gemm<3, true><<<gLog, t1>>>(ksp, DS, qs, DS, 0, lt, N, 0, (size_t)N * N,
                                    nullptr, 0, 0, kt, qt, N, HD);
    softmax_kernel<<<BH * N, 256>>>();
    av_kernel<<<dim3(16, BH), dim3(16, 16)>>>();

    // 4) hyperboloid normalize per head, concat heads, new time
    assemble_kernel<<<BN, 256>>>();

    // 5) Wo projection + residual with x (space part)
    mma_gemm<2, false><<<g768, t1>>>(attn, D, Wo, D, 1, out1, DS, 0, 0, x, D, 1, nullptr, nullptr, DS, D);

    // 6) LN2
    ln_kernel<<<BN, 256>>>(out1, DS, 0, gamma2, beta2, z);

    // 7) FFN up: gelu(z @ W1^T)[1:] -> hcat cols 1..3071 ; col 0 = time
    mma_gemm<1, false><<<gFF1, t1>>>(z, D, W1, D, 1, hcat, M_, 1, 0, nullptr, 0, 0, nullptr, nullptr, MS, D);
    hcat_time_kernel<<<BN, 256>>>();

    // 8) FFN down: (hcat @ W2^T)[1:] + out1 -> d_out space cols
    mma_gemm<2, false><<<g768, t1>>>(hcat, M_, W2, M_, 1, out, D, 1, 0, out1, DS, 0, nullptr, nullptr, DS, M_);

    // 9) final add_time
    final_time_kernel<<<BN, 256>>>(out);
}

// round 6
// speedup vs baseline: 4.1656x; 2.5814x over previous
#include <cuda_runtime.h>
#include <math.h>
#include <stdint.h>

// ---------------------------------------------------------------------------
// LorentzTransformerEncoder  (B=8, N=1024, D=769, H=12, hd=64, M=3072)
// R6 = cp.async 3-stage tf32 MMA pipeline (R4/R5 arch), defensive deltas:
//  - explicit MaxDynamicSharedMemorySize opt-in
//  - no device lambda
//  - no zero-size cp.async (clamped row + smem pre-zero for tail tiles)
// ---------------------------------------------------------------------------

constexpr int B  = 8;
constexpr int N  = 1024;
constexpr int DS = 768;
constexpr int H  = 12;
constexpr int HD = 64;
constexpr int M_ = 3072;
constexpr int BN = B * N;   // 8192
constexpr int BH = B * H;   // 96

// ------------------------------- scratch -----------------------------------
__device__ float g_h1s [(size_t)BN * DS];
__device__ float g_h1t [BN];
__device__ float g_qs  [(size_t)BN * DS];
__device__ float g_ksp [(size_t)BN * DS];
__device__ float g_vsp [(size_t)BN * DS];
__device__ float g_qt  [BH * N];
__device__ float g_kt  [BH * N];
__device__ float g_vT  [(size_t)BH * 80 * N];   // row 0 time, rows 1..64 space^T
__device__ float g_lt  [(size_t)BH * N * N];
__device__ float g_s   [(size_t)BH * N * 80];
__device__ float g_atns[(size_t)BN * DS];
__device__ float g_atnt[BN];
__device__ float g_out1[(size_t)BN * DS];
__device__ float g_zs  [(size_t)BN * DS];
__device__ float g_zt  [BN];
__device__ float g_hid [(size_t)BN * M_];       // col 3071 stays 0
__device__ float g_hidt[BN];
// tf32 weights (space part, k-major, aligned) + time columns
__device__ float g_wqs [768 * 768];  __device__ float g_wqt [768];
__device__ float g_wks [768 * 768];  __device__ float g_wkt [768];
__device__ float g_wvs [768 * 768];  __device__ float g_wvt [768];
__device__ float g_wos [768 * 768];  __device__ float g_wot [768];
__device__ float g_w1s [3071 * 768]; __device__ float g_w1t [3071];
__device__ float g_w2s [768 * 3072]; __device__ float g_w2t [768];

// ----------------------------- helpers --------------------------------------
__device__ __forceinline__ uint32_t cvt_tf32(float x) {
    uint32_t r;
    asm("cvt.rna.tf32.f32 %0, %1;" : "=r"(r) : "f"(x));
    return r;
}
__device__ __forceinline__ float rnd_tf32(float x) { return __uint_as_float(cvt_tf32(x)); }

__device__ __forceinline__ void ldsm4(uint32_t& r0, uint32_t& r1, uint32_t& r2,
                                      uint32_t& r3, uint32_t addr) {
    asm volatile("ldmatrix.sync.aligned.m8n8.x4.shared.b16 {%0,%1,%2,%3},[%4];"
                 : "=r"(r0), "=r"(r1), "=r"(r2), "=r"(r3) : "r"(addr));
}
__device__ __forceinline__ void mma_tf32(float* c, const uint32_t* a, const uint32_t* b) {
    asm volatile("mma.sync.aligned.m16n8k8.row.col.f32.tf32.tf32.f32 "
                 "{%0,%1,%2,%3},{%4,%5,%6,%7},{%8,%9},{%0,%1,%2,%3};"
                 : "+f"(c[0]), "+f"(c[1]), "+f"(c[2]), "+f"(c[3])
                 : "r"(a[0]), "r"(a[1]), "r"(a[2]), "r"(a[3]), "r"(b[0]), "r"(b[1]));
}
#define CP16(d, s) \
    asm volatile("cp.async.cg.shared.global [%0],[%1],16;" :: "r"(d), "l"(s))
#define CP_COMMIT() asm volatile("cp.async.commit_group;" ::: "memory")
#define CP_WAIT1()  asm volatile("cp.async.wait_group 1;" ::: "memory")

// issue one pipeline stage (A rows bm..bm+127, B rows clamped to valid range)
#define ISSUE_STAGE(slot, k0)                                   \
    do {                                                        \
        uint32_t sa_ = sbase + (slot) * 16384 + dOff;           \
        CP16(sa_,         aSrc  + (k0));                        \
        CP16(sa_ + 4096,  aSrc2 + (k0));                        \
        CP16(sa_ + 8192,  bSrc1 + (k0));                        \
        CP16(sa_ + 12288, bSrc2 + (k0));                        \
        CP_COMMIT();                                            \
    } while (0)

__device__ __forceinline__ float block_reduce_sum(float v, float* sh) {
    int tid = threadIdx.x, lane = tid & 31, wid = tid >> 5;
    #pragma unroll
    for (int o = 16; o > 0; o >>= 1) v += __shfl_down_sync(0xffffffffu, v, o);
    __syncthreads();
    if (lane == 0) sh[wid] = v;
    __syncthreads();
    if (tid == 0) {
        float s = 0.f;
        #pragma unroll
        for (int w = 0; w < 8; w++) s += sh[w];
        sh[32] = s;
    }
    __syncthreads();
    return sh[32];
}
__device__ __forceinline__ float block_reduce_max(float v, float* sh) {
    int tid = threadIdx.x, lane = tid & 31, wid = tid >> 5;
    #pragma unroll
    for (int o = 16; o > 0; o >>= 1) v = fmaxf(v, __shfl_down_sync(0xffffffffu, v, o));
    __syncthreads();
    if (lane == 0) sh[wid] = v;
    __syncthreads();
    if (tid == 0) {
        float m = sh[0];
        #pragma unroll
        for (int w = 1; w < 8; w++) m = fmaxf(m, sh[w]);
        sh[32] = m;
    }
    __syncthreads();
    return sh[32];
}

// ------------------------ weight prep (tf32 + split time) -------------------
__global__ void prep_w(const float* __restrict__ W, float* __restrict__ Ws,
                       float* __restrict__ Wt, int rows, int cols, int kcols, int sld) {
    int idx = blockIdx.x * 256 + threadIdx.x;
    if (idx >= rows * cols) return;
    int n = idx / cols, k = idx - n * cols;
    float v = (k < kcols) ? W[(size_t)(n + 1) * sld + k + 1] : 0.f;
    Ws[idx] = rnd_tf32(v);
    if (k == 0) Wt[n] = W[(size_t)(n + 1) * sld];
}

// ------------------------- Lorentz layernorm --------------------------------
__global__ void ln_kernel(const float* __restrict__ X, int ldx, int xofs,
                          const float* __restrict__ gamma,
                          const float* __restrict__ beta,
                          float* __restrict__ Ys, float* __restrict__ Yt) {
    __shared__ float sh[33];
    int bn = blockIdx.x, tid = threadIdx.x;
    const float* x = X + (size_t)bn * ldx + xofs;
    float v[3], s = 0.f;
    #pragma unroll
    for (int i = 0; i < 3; i++) { v[i] = x[tid + i * 256]; s += v[i]; }
    s = block_reduce_sum(s, sh);
    float mu = s * (1.f / 768.f);
    float s2 = 0.f;
    #pragma unroll
    for (int i = 0; i < 3; i++) { float dd = v[i] - mu; s2 += dd * dd; }
    s2 = block_reduce_sum(s2, sh);
    float rstd = rsqrtf(s2 * (1.f / 768.f) + 1e-5f);
    float t2 = 0.f;
    float* ys = Ys + (size_t)bn * DS;
    #pragma unroll
    for (int i = 0; i < 3; i++) {
        int d = tid + i * 256;
        float yy = gamma[d] * (v[i] - mu) * rstd + beta[d];
        ys[d] = rnd_tf32(yy);
        t2 += yy * yy;
    }
    t2 = block_reduce_sum(t2, sh);
    if (tid == 0) Yt[bn] = sqrtf(1.f + t2);
}

// ------------------------------- tf32 GEMM ----------------------------------
// C[m][n] = sum_k A[m][k] * Bw[n][k]  (+ rank1 tA[m]*tB[n] if RK1)
// EPI: 0 none, 1 gelu, 2 +R, 3 lorentz-logit.  BM: 0 none, 1 head-slice, 2 flat
// 128x128 tile, K%16==0, 3-stage cp.async, 256 thr, 8 warps (2m x 4n).
// TAILN: Nn may be < 128*gridDim.x (B rows clamped; tail cols masked via tailMask)
template<int EPI, int BM, bool RK1, bool RND, bool TAILN>
__global__ void __launch_bounds__(256, 2)
mma_gemm(const float* __restrict__ A, int lda, size_t aBatch,
         const float* __restrict__ Bw, int ldb, size_t bBatch,
         float* __restrict__ C, int ldc, int cofs, size_t cBatch,
         const float* __restrict__ R, int ldr, int rofs,
         const float* __restrict__ tA, const float* __restrict__ tB,
         int Nn, int Kk) {
    extern __shared__ float dsm[];
    uint32_t sbase = (uint32_t)__cvta_generic_to_shared(dsm);

    int tid = threadIdx.x;
    int lane = tid & 31, wid = tid >> 5;
    int warpm = wid >> 2, warpn = wid & 3;
    int bm = blockIdx.y << 7, bnb = blockIdx.x << 7;

    const float* Ab = A;
    const float* Bb = Bw;
    const float* tAp = tA;
    const float* tBp = tB;
    float* Cp = C;
    if (BM == 1) {
        int bz = blockIdx.z;
        int b = bz / H, h = bz % H;
        Ab += (size_t)b * N * lda + h * HD;
        Bb += (size_t)b * N * ldb + h * HD;
        tAp = tA + (size_t)bz * N;
        tBp = tB + (size_t)bz * N;
        Cp += (size_t)bz * cBatch;
    }
    if (BM == 2) {
        int bz = blockIdx.z;
        Ab += (size_t)bz * aBatch;
        Bb += (size_t)bz * bBatch;
        Cp += (size_t)bz * cBatch;
    }

    // ---- loader constants: thread -> (row, chunk) pair, rows r and r+64 ----
    int lrow = tid >> 2, lch = tid & 3;
    uint32_t dOff = lrow * 64 + ((lch ^ ((lrow >> 1) & 3)) << 4);  // bytes
    const float* aSrc  = Ab + (size_t)(bm + lrow) * lda + lch * 4;
    const float* aSrc2 = aSrc + (size_t)64 * lda;
    int brow1 = bnb + lrow, brow2 = brow1 + 64;
    bool bok1 = brow1 < Nn, bok2 = brow2 < Nn;
    // clamp OOR rows to a valid row: loaded data is garbage but masked at epilogue
    int cb1 = bok1 ? brow1 : Nn - 1;
    int cb2 = bok2 ? brow2 : Nn - 1;
    const float* bSrc1 = Bb + (size_t)cb1 * ldb + lch * 4;
    const float* bSrc2 = Bb + (size_t)cb2 * ldb + lch * 4;

    // ---- ldmatrix lane addressing ----
    int lrowA = (lane & 7) + ((lane >> 3) & 1) * 8;   // 0..15
    int hiA   = lane >> 4;
    int swA   = (lrowA >> 1) & 3;
    int lrowB = (lane & 7) + ((lane >> 4) & 1) * 8;
    int hiB   = (lane >> 3) & 1;
    int swB   = (lrowB >> 1) & 3;
    uint32_t aOff[2], bOff[2];
    #pragma unroll
    for (int ks = 0; ks < 2; ks++) {
        aOff[ks] = (warpm * 64 + lrowA) * 64 + (((2 * ks + hiA) ^ swA) << 4);
        bOff[ks] = 8192 + (warpn * 32 + lrowB) * 64 + (((2 * ks + hiB) ^ swB) << 4);
    }

    float acc[4][4][4];
    #pragma unroll
    for (int i = 0; i < 4; i++)
        #pragma unroll
        for (int j = 0; j < 4; j++)
            #pragma unroll
            for (int r = 0; r < 4; r++) acc[i][j][r] = 0.f;

    int KT = Kk >> 4;

    ISSUE_STAGE(0, 0);
    ISSUE_STAGE(1, 16);

    for (int kt = 0; kt < KT; kt++) {
        CP_WAIT1();
        __syncthreads();
        int st = kt % 3;
        uint32_t sb = sbase + st * 16384;
        #pragma unroll
        for (int ks = 0; ks < 2; ks++) {
            uint32_t af[4][4];
            uint32_t bf[4][2];
            #pragma unroll
            for (int mt = 0; mt < 4; mt++)
                ldsm4(af[mt][0], af[mt][1], af[mt][2], af[mt][3],
                      sb + aOff[ks] + mt * 1024);
            #pragma unroll
            for (int np = 0; np < 2; np++)
                ldsm4(bf[2 * np][0], bf[2 * np][1], bf[2 * np + 1][0], bf[2 * np + 1][1],
                      sb + bOff[ks] + np * 1024);
            #pragma unroll
            for (int mt = 0; mt < 4; mt++)
                #pragma unroll
                for (int nt = 0; nt < 4; nt++)
                    mma_tf32(acc[mt][nt], af[mt], bf[nt]);
        }
        int nk = kt + 2;
        if (nk < KT) { ISSUE_STAGE(nk % 3, nk << 4); }
        else CP_COMMIT();
    }

    // ------------------------------ epilogue --------------------------------
    int er = bm + warpm * 64 + (lane >> 2);
    int ec0 = bnb + warpn * 32 + 2 * (lane & 3);
    #pragma unroll
    for (int mt = 0; mt < 4; mt++) {
        #pragma unroll
        for (int nt = 0; nt < 4; nt++) {
            #pragma unroll
            for (int half = 0; half < 2; half++) {
                int r = er + mt * 16 + half * 8;
                int c = ec0 + nt * 8;
                bool ok0 = !TAILN || c < Nn;
                bool ok1 = !TAILN || (c + 1) < Nn;
                float v0 = acc[mt][nt][2 * half];
                float v1 = acc[mt][nt][2 * half + 1];
                if (RK1) {
                    float ta = tAp[r];
                    if (ok0) v0 += ta * tBp[c];
                    if (ok1) v1 += ta * tBp[c + 1];
                }
                if (EPI == 1) {
                    float t0 = tanhf(0.7978845608028654f * (v0 + 0.044715f * v0 * v0 * v0));
                    v0 = 0.5f * v0 * (1.f + t0);
                    float t1 = tanhf(0.7978845608028654f * (v1 + 0.044715f * v1 * v1 * v1));
                    v1 = 0.5f * v1 * (1.f + t1);
                }
                if (EPI == 2) {
                    const float* rp = R + (size_t)r * ldr + rofs;
                    if (ok0) v0 += rp[c];
                    if (ok1) v1 += rp[c + 1];
                }
                if (EPI == 3) {
                    float kt_ = tAp[r];
                    float d20 = fmaxf(2.f * (kt_ * tBp[c] - v0 - 1.f), 1e-8f);
                    float d21 = fmaxf(2.f * (kt_ * tBp[ok1 ? c + 1 : c] - v1 - 1.f), 1e-8f);
                    v0 = 1.f / (1.f + log1pf(d20));
                    v1 = 1.f / (1.f + log1pf(d21));
                }
                if (RND) { v0 = rnd_tf32(v0); v1 = rnd_tf32(v1); }
                float* cp = Cp + (size_t)r * ldc + cofs;
                if (ok0) cp[c] = v0;
                if (ok1) cp[c + 1] = v1;
            }
        }
    }
}

// ----------------------- per-head time for Q, K -----------------------------
__global__ void head_time_kernel() {
    int idx = blockIdx.x * 256 + threadIdx.x;
    if (idx >= BH * N) return;
    int which = blockIdx.y;
    int i = idx & (N - 1);
    int bh = idx >> 10;
    int h = bh % H, b = bh / H;
    const float* S = which ? g_ksp : g_qs;
    float* T = which ? g_kt : g_qt;
    const float* p = S + (size_t)(b * N + i) * DS + h * HD;
    float s = 1.f;
    #pragma unroll 16
    for (int d = 0; d < HD; d++) s = fmaf(p[d], p[d], s);
    T[idx] = sqrtf(s);
}

// ------------------ V transpose to [bh][80][N] (rows 1..64) -----------------
__global__ void vT_kernel() {
    __shared__ float tile[32][33];
    int i0 = blockIdx.x << 5, d0 = blockIdx.y << 5, b = blockIdx.z;
    int tx = threadIdx.x, ty = threadIdx.y;
    #pragma unroll
    for (int r = 0; r < 4; r++)
        tile[ty + 8 * r][tx] = g_vsp[(size_t)(b * N + i0 + ty + 8 * r) * DS + d0 + tx];
    __syncthreads();
    #pragma unroll
    for (int r = 0; r < 4; r++) {
        int dg = d0 + ty + 8 * r;
        int h = dg >> 6, dd = dg & 63;
        g_vT[((size_t)(b * H + h) * 80 + 1 + dd) * N + i0 + tx] = tile[tx][ty + 8 * r];
    }
}

// ----------------- V time into row 0 of g_vT (tf32-rounded) -----------------
__global__ void vtime_kernel() {
    int idx = blockIdx.x * 256 + threadIdx.x;
    if (idx >= BH * N) return;
    int bh = idx >> 10, i = idx & (N - 1);
    const float* p = g_vT + (size_t)bh * 80 * N + N + i;
    float s = 1.f;
    #pragma unroll 16
    for (int d = 0; d < HD; d++) { float v = p[(size_t)d * N]; s = fmaf(v, v, s); }
    g_vT[(size_t)bh * 80 * N + i] = rnd_tf32(sqrtf(s));
}

// ----------------------------- softmax --------------------------------------
__global__ void softmax_kernel() {
    __shared__ float sh[33];
    size_t row = blockIdx.x;
    float* p = g_lt + row * N;
    int tid = threadIdx.x;
    float v[4], mx = -1e30f;
    #pragma unroll
    for (int i = 0; i < 4; i++) { v[i] = p[tid + i * 256]; mx = fmaxf(mx, v[i]); }
    mx = block_reduce_max(mx, sh);
    float s = 0.f;
    #pragma unroll
    for (int i = 0; i < 4; i++) { v[i] = expf(v[i] - mx); s += v[i]; }
    s = block_reduce_sum(s, sh);
    float inv = 1.f / s;
    #pragma unroll
    for (int i = 0; i < 4; i++) p[tid + i * 256] = rnd_tf32(v[i] * inv);
}

// --------- per-head hyperboloid normalize + head-concat + new time ----------
__global__ void assemble_kernel() {
    __shared__ float hsum[12];
    __shared__ float hinv[12];
    __shared__ float cts;
    int bn = blockIdx.x;
    int b = bn >> 10, j = bn & (N - 1);
    int tid = threadIdx.x;
    if (tid < 12) hsum[tid] = 0.f;
    if (tid == 0) cts = 0.f;
    __syncthreads();
    float sv[3];
    #pragma unroll
    for (int r = 0; r < 3; r++) {
        int e = tid + r * 256;
        int h = e >> 6, d = e & 63;
        sv[r] = g_s[((size_t)(b * H + h) * N + j) * 80 + 1 + d];
        atomicAdd(&hsum[h], sv[r] * sv[r]);
    }
    __syncthreads();
    if (tid < 12) {
        float st = g_s[((size_t)(b * H + tid) * N + j) * 80];
        float li = st * st - hsum[tid];
        float inv = rsqrtf(fmaxf(li, 1e-8f));
        hinv[tid] = inv;
        float ct = st * inv;
        atomicAdd(&cts, ct * ct);
    }
    __syncthreads();
    float* os = g_atns + (size_t)bn * DS;
    #pragma unroll
    for (int r = 0; r < 3; r++) {
        int e = tid + r * 256;
        int h = e >> 6;
        os[e] = rnd_tf32(sv[r] * hinv[h]);
    }
    if (tid == 0) g_atnt[bn] = sqrtf(cts - 11.f);
}

// --------------------- FFN hidden time --------------------------------------
__global__ void hid_time_kernel() {
    __shared__ float sh[33];
    int bn = blockIdx.x, tid = threadIdx.x;
    const float* p = g_hid + (size_t)bn * M_;
    float s = 0.f;
    for (int d = tid; d < 3071; d += 256) s = fmaf(p[d], p[d], s);
    s = block_reduce_sum(s, sh);
    if (tid == 0) g_hidt[bn] = sqrtf(1.f + s);
}

// --------------------------- final add_time ---------------------------------
__global__ void final_time_kernel(float* __restrict__ out) {
    __shared__ float sh[33];
    int bn = blockIdx.x, tid = threadIdx.x;
    float* p = out + (size_t)bn * 769;
    float s = 0.f;
    #pragma unroll
    for (int r = 0; r < 3; r++) {
        float v = p[1 + tid + r * 256];
        s = fmaf(v, v, s);
    }
    s = block_reduce_sum(s, sh);
    if (tid == 0) p[0] = sqrtf(1.f + s);
}

// ----------------------------------------------------------------------------
extern "C" void kernel_launch(void* const* d_in, const int* in_sizes, int n_in,
                              void* d_out, int out_size) {
    const float* x      = (const float*)d_in[0];
    const float* gamma1 = (const float*)d_in[1];
    const float* beta1  = (const float*)d_in[2];
    const float* Wq     = (const float*)d_in[3];
    const float* Wk     = (const float*)d_in[4];
    const float* Wv     = (const float*)d_in[5];
    const float* Wo     = (const float*)d_in[6];
    const float* gamma2 = (const float*)d_in[7];
    const float* beta2  = (const float*)d_in[8];
    const float* W1     = (const float*)d_in[9];
    const float* W2     = (const float*)d_in[10];
    float* out = (float*)d_out;

    float *h1s, *h1t, *qs, *ksp, *vsp, *qt, *kt, *vT, *lt, *s_, *atns, *atnt;
    float *out1, *zs, *zt, *hid, *hidt;
    float *wqs, *wqt, *wks, *wkt, *wvs, *wvt, *wos, *wot, *w1s, *w1t, *w2s, *w2t;
    cudaGetSymbolAddress((void**)&h1s,  g_h1s);  cudaGetSymbolAddress((void**)&h1t,  g_h1t);
    cudaGetSymbolAddress((void**)&qs,   g_qs);   cudaGetSymbolAddress((void**)&ksp,  g_ksp);
    cudaGetSymbolAddress((void**)&vsp,  g_vsp);
    cudaGetSymbolAddress((void**)&qt,   g_qt);   cudaGetSymbolAddress((void**)&kt,   g_kt);
    cudaGetSymbolAddress((void**)&vT,   g_vT);   cudaGetSymbolAddress((void**)&lt,   g_lt);
    cudaGetSymbolAddress((void**)&s_,   g_s);
    cudaGetSymbolAddress((void**)&atns, g_atns); cudaGetSymbolAddress((void**)&atnt, g_atnt);
    cudaGetSymbolAddress((void**)&out1, g_out1);
    cudaGetSymbolAddress((void**)&zs,   g_zs);   cudaGetSymbolAddress((void**)&zt,   g_zt);
    cudaGetSymbolAddress((void**)&hid,  g_hid);  cudaGetSymbolAddress((void**)&hidt, g_hidt);
    cudaGetSymbolAddress((void**)&wqs,  g_wqs);  cudaGetSymbolAddress((void**)&wqt,  g_wqt);
    cudaGetSymbolAddress((void**)&wks,  g_wks);  cudaGetSymbolAddress((void**)&wkt,  g_wkt);
    cudaGetSymbolAddress((void**)&wvs,  g_wvs);  cudaGetSymbolAddress((void**)&wvt,  g_wvt);
    cudaGetSymbolAddress((void**)&wos,  g_wos);  cudaGetSymbolAddress((void**)&wot,  g_wot);
    cudaGetSymbolAddress((void**)&w1s,  g_w1s);  cudaGetSymbolAddress((void**)&w1t,  g_w1t);
    cudaGetSymbolAddress((void**)&w2s,  g_w2s);  cudaGetSymbolAddress((void**)&w2t,  g_w2t);

    constexpr int SMB = 49152;   // 3 stages * 16KB
    // explicit opt-in (idempotent; defensive vs at-the-limit default)
    cudaFuncSetAttribute(mma_gemm<0, 0, true,  true,  false>, cudaFuncAttributeMaxDynamicSharedMemorySize, SMB);
    cudaFuncSetAttribute(mma_gemm<3, 1, false, false, false>, cudaFuncAttributeMaxDynamicSharedMemorySize, SMB);
    cudaFuncSetAttribute(mma_gemm<0, 2, false, false, true>,  cudaFuncAttributeMaxDynamicSharedMemorySize, SMB);
    cudaFuncSetAttribute(mma_gemm<2, 0, true,  false, false>, cudaFuncAttributeMaxDynamicSharedMemorySize, SMB);
    cudaFuncSetAttribute(mma_gemm<1, 0, true,  true,  true>,  cudaFuncAttributeMaxDynamicSharedMemorySize, SMB);

    dim3 t1(256);

    // 0) weight prep (tf32-rounded, aligned, time split)
    prep_w<<<(768 * 768 + 255) / 256, t1>>>(Wq, wqs, wqt, 768, 768, 768, 769);
    prep_w<<<(768 * 768 + 255) / 256, t1>>>(Wk, wks, wkt, 768, 768, 768, 769);
    prep_w<<<(768 * 768 + 255) / 256, t1>>>(Wv, wvs, wvt, 768, 768, 768, 769);
    prep_w<<<(768 * 768 + 255) / 256, t1>>>(Wo, wos, wot, 768, 768, 768, 769);
    prep_w<<<(3071 * 768 + 255) / 256, t1>>>(W1, w1s, w1t, 3071, 768, 768, 769);
    prep_w<<<(768 * 3072 + 255) / 256, t1>>>(W2, w2s, w2t, 768, 3072, 3071, 3072);

    // 1) LN1
    ln_kernel<<<BN, t1>>>(x, 769, 1, gamma1, beta1, h1s, h1t);

    // 2) QKV (rank-1 time col, rounded output)
    mma_gemm<0, 0, true, true, false><<<dim3(6, 64), t1, SMB>>>(
        h1s, 768, 0, wqs, 768, 0, qs, 768, 0, 0, nullptr, 0, 0, h1t, wqt, 768, 768);
    mma_gemm<0, 0, true, true, false><<<dim3(6, 64), t1, SMB>>>(
        h1s, 768, 0, wks, 768, 0, ksp, 768, 0, 0, nullptr, 0, 0, h1t, wkt, 768, 768);
    mma_gemm<0, 0, true, true, false><<<dim3(6, 64), t1, SMB>>>(
        h1s, 768, 0, wvs, 768, 0, vsp, 768, 0, 0, nullptr, 0, 0, h1t, wvt, 768, 768);
    head_time_kernel<<<dim3((BH * N + 255) / 256, 2), t1>>>();
    vT_kernel<<<dim3(32, 24, 8), dim3(32, 8)>>>();
    vtime_kernel<<<(BH * N + 255) / 256, t1>>>();

    // 3) logits (transposed), softmax, P @ V_cat
    mma_gemm<3, 1, false, false, false><<<dim3(8, 8, BH), t1, SMB>>>(
        ksp, 768, 0, qs, 768, 0, lt, N, 0, (size_t)N * N, nullptr, 0, 0, kt, qt, N, HD);
    softmax_kernel<<<BH * N, t1>>>();
    mma_gemm<0, 2, false, false, true><<<dim3(1, 8, BH), t1, SMB>>>(
        lt, N, (size_t)N * N, vT, N, (size_t)80 * N, s_, 80, 0, (size_t)N * 80,
        nullptr, 0, 0, nullptr, nullptr, 65, N);

    // 4) normalize + concat heads
    assemble_kernel<<<BN, t1>>>();

    // 5) Wo + residual(x)
    mma_gemm<2, 0, true, false, false><<<dim3(6, 64), t1, SMB>>>(
        atns, 768, 0, wos, 768, 0, out1, 768, 0, 0, x, 769, 1, atnt, wot, 768, 768);

    // 6) LN2
    ln_kernel<<<BN, t1>>>(out1, 768, 0, gamma2, beta2, zs, zt);

    // 7) FFN up (gelu, rounded)
    mma_gemm<1, 0, true, true, true><<<dim3(24, 64), t1, SMB>>>(
        zs, 768, 0, w1s, 768, 0, hid, M_, 0, 0, nullptr, 0, 0, zt, w1t, 3071, 768);
    hid_time_kernel<<<BN, t1>>>();

    // 8) FFN down + residual(out1) -> d_out space cols
    mma_gemm<2, 0, true, false, false><<<dim3(6, 64), t1, SMB>>>(
        hid, M_, 0, w2s, M_, 0, out, 769, 1, 0, out1, 768, 0, hidt, w2t, 768, M_);

    // 9) final add_time
    final_time_kernel<<<BN, t1>>>(out);
}